// round 5
// baseline (speedup 1.0000x reference)
#include <cuda_runtime.h>
#include <cstdint>
#include <cstddef>

// 3-layer LSTM (H=64), S=2048, B=512, FC(64->2).
// rec: 4 independent 128-thread groups per CTA (1 batch row each), named
//      barriers only, full-K dot products per thread -> zero shuffles.
// proj: time-parallel Wih GEMM into g_xp[row][256] (plain layout), shuffle-
//       free, double-buffered smem, coalesced reads+writes.

#define SQ   2048
#define BB   512
#define HID  64

static __device__ float g_bufA[(size_t)SQ * BB * HID];   // layer0 h
static __device__ float g_bufB[(size_t)SQ * BB * HID];   // layer1 h
static __device__ float g_xp  [(size_t)SQ * BB * 256];   // xp, plain cols

__device__ __forceinline__ unsigned long long fma2(unsigned long long a,
                                                   unsigned long long b,
                                                   unsigned long long c) {
    unsigned long long d;
    asm("fma.rn.f32x2 %0, %1, %2, %3;" : "=l"(d) : "l"(a), "l"(b), "l"(c));
    return d;
}
__device__ __forceinline__ float lohi(unsigned long long u) {
    union { unsigned long long v; float2 f; } c; c.v = u;
    return c.f.x + c.f.y;
}
__device__ __forceinline__ float ex2a(float x) {
    float y; asm("ex2.approx.f32 %0, %1;" : "=f"(y) : "f"(x)); return y;
}
__device__ __forceinline__ float rcpa(float x) {
    float y; asm("rcp.approx.f32 %0, %1;" : "=f"(y) : "f"(x)); return y;
}
__device__ __forceinline__ float sigf(float x) {
    return rcpa(1.0f + ex2a(-1.4426950408889634f * x));
}
__device__ __forceinline__ float tanh_(float x) {
    return 2.0f * rcpa(1.0f + ex2a(-2.8853900817779268f * x)) - 1.0f;
}

// ---------------------------------------------------------------------------
// Recurrence. grid=128 CTAs x 512 threads. Group grp=tid>>7 owns batch
// b = 4*blockIdx.x + grp. Thread gt=tid&127 owns gate rows (gt, gt+128),
// full K=64 (128 weight floats in regs). Steps synced by bar.sync(grp+1,128).
// MODE: 0 = layer0 (x inline, h->bufA), 1 = mid (xp in, h->bufB),
//       2 = final (xp in, FC->out).
// ---------------------------------------------------------------------------
template <int MODE>
__global__ void __launch_bounds__(512, 1)
lstm_rec(const float* __restrict__ xin,
         const float* __restrict__ Wih, const float* __restrict__ Whh,
         const float* __restrict__ bih, const float* __restrict__ bhh,
         const float* __restrict__ fcw, const float* __restrict__ fcb,
         float* __restrict__ out)
{
    __shared__ __align__(16) float hsm[4][72];
    __shared__ float gsm[4][256];
    __shared__ __align__(16) float xsm[4][2][4];     // MODE 0 only

    const int tid = threadIdx.x;
    const int grp = tid >> 7;
    const int gt  = tid & 127;
    const int b   = blockIdx.x * 4 + grp;
    const int r0  = gt, r1 = gt + 128;

    // full-K weight rows (f32x2 packed): 64 regs
    unsigned long long w0[32], w1[32];
#pragma unroll
    for (int k2 = 0; k2 < 32; k2++) {
        w0[k2] = *(const unsigned long long*)(Whh + (size_t)r0 * HID + 2 * k2);
        w1[k2] = *(const unsigned long long*)(Whh + (size_t)r1 * HID + 2 * k2);
    }
    float4 wi0, wi1; float bias0 = 0.f, bias1 = 0.f;
    if (MODE == 0) {
        wi0 = *(const float4*)(Wih + (size_t)r0 * 4);
        wi1 = *(const float4*)(Wih + (size_t)r1 * 4);
        bias0 = bih[r0] + bhh[r0];
        bias1 = bih[r1] + bhh[r1];
    }

    const bool upd = (gt < HID);
    float c = 0.f;
    if (upd) hsm[grp][gt] = 0.f;

    // xp prefetch (distance 2)
    const float* xpp = g_xp + (size_t)b * 256;
    const size_t xstride = (size_t)BB * 256;
    float xq0 = 0.f, xq1 = 0.f, xm0 = 0.f, xm1 = 0.f;
    if (MODE != 0) {
        xq0 = xpp[r0];            xq1 = xpp[r1];
        xm0 = xpp[xstride + r0];  xm1 = xpp[xstride + r1];
    } else if (gt == 0) {
        *(float4*)xsm[grp][0] = *(const float4*)(xin + (size_t)b * SQ * 4);
    }
    __syncthreads();

    float* dst = (MODE == 0) ? g_bufA : g_bufB;

    for (int t = 0; t < SQ; t++) {
        // prefetch t+2 (MODE!=0) / t+1 (MODE 0 x)
        float xn0 = 0.f, xn1 = 0.f; float4 xnv;
        if (MODE != 0) {
            if (t + 2 < SQ) {
                const float* p = xpp + (size_t)(t + 2) * xstride;
                xn0 = p[r0]; xn1 = p[r1];
            }
        } else if (gt == 0 && t + 1 < SQ) {
            xnv = *(const float4*)(xin + ((size_t)b * SQ + t + 1) * 4);
        }

        // ---- full-K dot products for rows r0, r1 ----
        unsigned long long a0 = 0ULL, a1 = 0ULL, c0a = 0ULL, c1a = 0ULL;
#pragma unroll
        for (int m = 0; m < 16; m++) {
            ulonglong2 hv = *(const ulonglong2*)(&hsm[grp][4 * m]);
            a0  = fma2(w0[2 * m],     hv.x, a0);
            a1  = fma2(w0[2 * m + 1], hv.y, a1);
            c0a = fma2(w1[2 * m],     hv.x, c0a);
            c1a = fma2(w1[2 * m + 1], hv.y, c1a);
        }
        float pre0 = lohi(a0) + lohi(a1);
        float pre1 = lohi(c0a) + lohi(c1a);
        if (MODE == 0) {
            const float* xa = xsm[grp][t & 1];
            pre0 += bias0 + wi0.x * xa[0] + wi0.y * xa[1] + wi0.z * xa[2] + wi0.w * xa[3];
            pre1 += bias1 + wi1.x * xa[0] + wi1.y * xa[1] + wi1.z * xa[2] + wi1.w * xa[3];
        } else {
            pre0 += xq0; pre1 += xq1;
        }
        // r0 in {i,f} -> sigmoid ; r1 in {g,o} -> tanh if gt<64 else sigmoid
        float ac0 = sigf(pre0);
        float ac1 = (gt < 64) ? tanh_(pre1) : sigf(pre1);
        gsm[grp][r0] = ac0;
        gsm[grp][r1] = ac1;
        asm volatile("bar.sync %0, 128;" :: "r"(grp + 1) : "memory");

        if (upd) {
            float iv = gsm[grp][gt];
            float fv = gsm[grp][gt + 64];
            float gv = gsm[grp][gt + 128];
            float ov = gsm[grp][gt + 192];
            c = fv * c + iv * gv;
            float h = ov * tanh_(c);
            hsm[grp][gt] = h;
            if (MODE != 2)
                dst[((size_t)t * BB + b) * HID + gt] = h;
        }
        if (MODE == 0) {
            if (gt == 0 && t + 1 < SQ) *(float4*)xsm[grp][(t + 1) & 1] = xnv;
        } else {
            xq0 = xm0; xq1 = xm1; xm0 = xn0; xm1 = xn1;
        }
        asm volatile("bar.sync %0, 128;" :: "r"(grp + 1) : "memory");
    }

    if (MODE == 2) {
        if (gt < 2) {
            int o = gt;
            float s = fcb[o];
#pragma unroll
            for (int j = 0; j < HID; j++)
                s += hsm[grp][j] * fcw[o * HID + j];
            out[b * 2 + o] = s;
        }
    }
}

// ---------------------------------------------------------------------------
// Projection: g_xp[row][r] = Wih[r,:] . src[row,:] + bih[r] + bhh[r]
// grid=1024 x 512. Thread: gt=tid&127 -> rows (gt,gt+128) full K,
// rq=tid>>7 -> row slot in a 4-row block. Double-buffered smem, 1 bar/block.
// ---------------------------------------------------------------------------
#define PCTAS 1024
#define PROWS ((SQ * BB) / PCTAS)     // 1024
#define PITER (PROWS / 4)             // 256

template <int SRCB>
__global__ void __launch_bounds__(512, 1)
lstm_proj(const float* __restrict__ Wih,
          const float* __restrict__ bih, const float* __restrict__ bhh)
{
    const float* src = (SRCB == 0) ? g_bufA : g_bufB;
    __shared__ __align__(16) float xr[2][4][72];

    const int tid = threadIdx.x;
    const int gt  = tid & 127;
    const int rq  = tid >> 7;
    const int r0  = gt, r1 = gt + 128;

    unsigned long long w0[32], w1[32];
#pragma unroll
    for (int k2 = 0; k2 < 32; k2++) {
        w0[k2] = *(const unsigned long long*)(Wih + (size_t)r0 * HID + 2 * k2);
        w1[k2] = *(const unsigned long long*)(Wih + (size_t)r1 * HID + 2 * k2);
    }
    const float bias0 = bih[r0] + bhh[r0];
    const float bias1 = bih[r1] + bhh[r1];

    const size_t row0 = (size_t)blockIdx.x * PROWS;

    float2 ld = make_float2(0.f, 0.f);
    if (tid < 128) {
        ld = *(const float2*)(src + (row0 + (tid >> 5)) * HID + 2 * (tid & 31));
        *(float2*)(&xr[0][tid >> 5][2 * (tid & 31)]) = ld;
    }
    __syncthreads();

    for (int it = 0; it < PITER; it++) {
        const int p = it & 1;
        const size_t rb = row0 + (size_t)it * 4;

        if (it + 1 < PITER && tid < 128)
            ld = *(const float2*)(src + (rb + 4 + (tid >> 5)) * HID + 2 * (tid & 31));

        unsigned long long a0 = 0ULL, a1 = 0ULL, c0a = 0ULL, c1a = 0ULL;
#pragma unroll
        for (int m = 0; m < 16; m++) {
            ulonglong2 hv = *(const ulonglong2*)(&xr[p][rq][4 * m]);
            a0  = fma2(w0[2 * m],     hv.x, a0);
            a1  = fma2(w0[2 * m + 1], hv.y, a1);
            c0a = fma2(w1[2 * m],     hv.x, c0a);
            c1a = fma2(w1[2 * m + 1], hv.y, c1a);
        }
        float v0 = lohi(a0) + lohi(a1) + bias0;
        float v1 = lohi(c0a) + lohi(c1a) + bias1;
        float* orow = g_xp + (rb + rq) * 256;
        orow[r0] = v0;
        orow[r1] = v1;

        if (it + 1 < PITER && tid < 128)
            *(float2*)(&xr[p ^ 1][tid >> 5][2 * (tid & 31)]) = ld;
        __syncthreads();
    }
}

extern "C" void kernel_launch(void* const* d_in, const int* in_sizes, int n_in,
                              void* d_out, int out_size)
{
    (void)in_sizes; (void)n_in; (void)out_size;
    const float* x    = (const float*)d_in[0];
    const float* Wih0 = (const float*)d_in[1];
    const float* Whh0 = (const float*)d_in[2];
    const float* bih0 = (const float*)d_in[3];
    const float* bhh0 = (const float*)d_in[4];
    const float* Wih1 = (const float*)d_in[5];
    const float* Whh1 = (const float*)d_in[6];
    const float* bih1 = (const float*)d_in[7];
    const float* bhh1 = (const float*)d_in[8];
    const float* Wih2 = (const float*)d_in[9];
    const float* Whh2 = (const float*)d_in[10];
    const float* bih2 = (const float*)d_in[11];
    const float* bhh2 = (const float*)d_in[12];
    const float* fc_w = (const float*)d_in[13];
    const float* fc_b = (const float*)d_in[14];
    float* out = (float*)d_out;

    dim3 rgrid(BB / 4), rblock(512);
    dim3 pgrid(PCTAS), pblock(512);

    lstm_rec<0><<<rgrid, rblock>>>(x, Wih0, Whh0, bih0, bhh0, nullptr, nullptr, nullptr);
    lstm_proj<0><<<pgrid, pblock>>>(Wih1, bih1, bhh1);
    lstm_rec<1><<<rgrid, rblock>>>(nullptr, nullptr, Whh1, nullptr, nullptr, nullptr, nullptr, nullptr);
    lstm_proj<1><<<pgrid, pblock>>>(Wih2, bih2, bhh2);
    lstm_rec<2><<<rgrid, rblock>>>(nullptr, nullptr, Whh2, nullptr, nullptr, fc_w, fc_b, out);
}

// round 6
// speedup vs baseline: 2.3758x; 2.3758x over previous
#include <cuda_runtime.h>
#include <cstdint>
#include <cstddef>

// 3-layer LSTM (H=64), S=2048, B=512, FC(64->2).
// rec: 2 groups x 256 threads per CTA, group owns 2 batch rows; thread owns
//      ONE gate row full-K (32 ull = 64 weight regs -> NO SPILLS), zero
//      shuffles, named group barriers.
// proj: time-parallel Wih GEMM into g_xp[row][256]; thread owns one row
//      (64 weight regs), 8 data rows/iter split across tid bit 8.

#define SQ   2048
#define BB   512
#define HID  64

static __device__ float g_bufA[(size_t)SQ * BB * HID];
static __device__ float g_bufB[(size_t)SQ * BB * HID];
static __device__ float g_xp  [(size_t)SQ * BB * 256];

__device__ __forceinline__ unsigned long long fma2(unsigned long long a,
                                                   unsigned long long b,
                                                   unsigned long long c) {
    unsigned long long d;
    asm("fma.rn.f32x2 %0, %1, %2, %3;" : "=l"(d) : "l"(a), "l"(b), "l"(c));
    return d;
}
__device__ __forceinline__ float lohi(unsigned long long u) {
    union { unsigned long long v; float2 f; } c; c.v = u;
    return c.f.x + c.f.y;
}
__device__ __forceinline__ float ex2a(float x) {
    float y; asm("ex2.approx.f32 %0, %1;" : "=f"(y) : "f"(x)); return y;
}
__device__ __forceinline__ float rcpa(float x) {
    float y; asm("rcp.approx.f32 %0, %1;" : "=f"(y) : "f"(x)); return y;
}
__device__ __forceinline__ float sigf(float x) {
    return rcpa(1.0f + ex2a(-1.4426950408889634f * x));
}
__device__ __forceinline__ float tanh_(float x) {
    return 2.0f * rcpa(1.0f + ex2a(-2.8853900817779268f * x)) - 1.0f;
}

// ---------------------------------------------------------------------------
// Recurrence. grid=128 CTAs x 512 threads.
// grp = tid>>8 (2 groups); group owns local batches {2grp, 2grp+1}
// (global b = 4*blockIdx.x + local). Thread r = tid&255 owns gate row r,
// computes its pre-activation for both batches. Steps synced with
// bar.sync(grp+1, 256). Update threads r<128 keep c in a register.
// MODE: 0 = layer0 (x inline, h->bufA), 1 = mid (xp in, h->bufB),
//       2 = final (xp in, FC->out).
// ---------------------------------------------------------------------------
template <int MODE>
__global__ void __launch_bounds__(512, 1)
lstm_rec(const float* __restrict__ xin,
         const float* __restrict__ Wih, const float* __restrict__ Whh,
         const float* __restrict__ bih, const float* __restrict__ bhh,
         const float* __restrict__ fcw, const float* __restrict__ fcb,
         float* __restrict__ out)
{
    __shared__ __align__(16) float hsm[4][72];     // 4 local batches
    __shared__ float gsm[4][256];
    __shared__ __align__(16) float4 xsm[2][4];     // MODE 0: [buf][local batch]

    const int tid = threadIdx.x;
    const int grp = tid >> 8;
    const int r   = tid & 255;
    const int blk = 2 * grp;                        // local batch base
    const int gb0 = blockIdx.x * 4 + blk;           // global batch of blk

    // one full-K weight row: 32 ull = 64 regs
    unsigned long long w[32];
#pragma unroll
    for (int k2 = 0; k2 < 32; k2++)
        w[k2] = *(const unsigned long long*)(Whh + (size_t)r * HID + 2 * k2);

    float4 wi; float bias = 0.f;
    if (MODE == 0) {
        wi = *(const float4*)(Wih + (size_t)r * 4);
        bias = bih[r] + bhh[r];
    }

    const bool upd = (r < 128);
    const int ubl = blk + (r >> 6);                 // local batch for update
    const int uj  = r & 63;
    float c = 0.f;
    if (upd) hsm[ubl][uj] = 0.f;

    const int gate = r >> 6;                        // 2 -> tanh

    // xp prefetch queue (distance 2) for both batches
    const size_t xstride = (size_t)BB * 256;
    const float* xp0 = g_xp + (size_t)gb0 * 256 + r;
    const float* xp1 = xp0 + 256;
    float xq0 = 0.f, xq1 = 0.f, xm0 = 0.f, xm1 = 0.f;
    if (MODE != 0) {
        xq0 = xp0[0];        xq1 = xp1[0];
        xm0 = xp0[xstride];  xm1 = xp1[xstride];
    } else if (r < 2) {
        xsm[0][blk + r] = *(const float4*)(xin + (size_t)(gb0 + r) * SQ * 4);
    }
    __syncthreads();

    float* dst = (MODE == 0) ? g_bufA : g_bufB;

    for (int t = 0; t < SQ; t++) {
        // prefetch t+2 xp / t+1 x
        float xn0 = 0.f, xn1 = 0.f; float4 xnv;
        if (MODE != 0) {
            if (t + 2 < SQ) {
                xn0 = xp0[(size_t)(t + 2) * xstride];
                xn1 = xp1[(size_t)(t + 2) * xstride];
            }
        } else if (r < 2 && t + 1 < SQ) {
            xnv = *(const float4*)(xin + ((size_t)(gb0 + r) * SQ + t + 1) * 4);
        }

        // ---- row-r dot products for both batches (broadcast LDS) ----
        unsigned long long a00 = 0ULL, a01 = 0ULL, a10 = 0ULL, a11 = 0ULL;
#pragma unroll
        for (int m = 0; m < 16; m++) {
            ulonglong2 h0 = *(const ulonglong2*)(&hsm[blk][4 * m]);
            ulonglong2 h1 = *(const ulonglong2*)(&hsm[blk + 1][4 * m]);
            a00 = fma2(w[2 * m],     h0.x, a00);
            a01 = fma2(w[2 * m + 1], h0.y, a01);
            a10 = fma2(w[2 * m],     h1.x, a10);
            a11 = fma2(w[2 * m + 1], h1.y, a11);
        }
        float pre0 = lohi(a00) + lohi(a01);
        float pre1 = lohi(a10) + lohi(a11);
        if (MODE == 0) {
            float4 xa = xsm[t & 1][blk];
            float4 xb = xsm[t & 1][blk + 1];
            pre0 += bias + wi.x * xa.x + wi.y * xa.y + wi.z * xa.z + wi.w * xa.w;
            pre1 += bias + wi.x * xb.x + wi.y * xb.y + wi.z * xb.z + wi.w * xb.w;
        } else {
            pre0 += xq0; pre1 += xq1;
        }
        gsm[blk][r]     = (gate == 2) ? tanh_(pre0) : sigf(pre0);
        gsm[blk + 1][r] = (gate == 2) ? tanh_(pre1) : sigf(pre1);
        asm volatile("bar.sync %0, 256;" :: "r"(grp + 1) : "memory");

        if (upd) {
            float iv = gsm[ubl][uj];
            float fv = gsm[ubl][uj + 64];
            float gv = gsm[ubl][uj + 128];
            float ov = gsm[ubl][uj + 192];
            c = fv * c + iv * gv;
            float h = ov * tanh_(c);
            hsm[ubl][uj] = h;
            if (MODE != 2)
                dst[((size_t)t * BB + gb0 + (r >> 6)) * HID + uj] = h;
        }
        if (MODE == 0) {
            if (r < 2 && t + 1 < SQ) xsm[(t + 1) & 1][blk + r] = xnv;
        } else {
            xq0 = xm0; xq1 = xm1; xm0 = xn0; xm1 = xn1;
        }
        asm volatile("bar.sync %0, 256;" :: "r"(grp + 1) : "memory");
    }

    if (MODE == 2) {
        if (r < 4) {
            int bsel = blk + (r >> 1), o = r & 1;
            float s = fcb[o];
#pragma unroll
            for (int j = 0; j < HID; j++)
                s += hsm[bsel][j] * fcw[o * HID + j];
            out[(blockIdx.x * 4 + bsel) * 2 + o] = s;
        }
    }
}

// ---------------------------------------------------------------------------
// Projection: g_xp[row][r] = Wih[r,:] . src[row,:] + bih[r] + bhh[r]
// grid=1024 x 512. Thread: r = tid&255 owns row r (full K, 64 weight regs);
// half = tid>>8 selects data rows {4*half .. 4*half+3} of each 8-row block.
// Double-buffered smem, 1 barrier/iter, coalesced reads and writes.
// ---------------------------------------------------------------------------
#define PCTAS 1024
#define PROWS ((SQ * BB) / PCTAS)     // 1024
#define PITER (PROWS / 8)             // 128

template <int SRCB>
__global__ void __launch_bounds__(512, 1)
lstm_proj(const float* __restrict__ Wih,
          const float* __restrict__ bih, const float* __restrict__ bhh)
{
    const float* src = (SRCB == 0) ? g_bufA : g_bufB;
    __shared__ __align__(16) float xr[2][8][72];

    const int tid  = threadIdx.x;
    const int r    = tid & 255;
    const int half = tid >> 8;
    const int rl0  = 4 * half;

    unsigned long long w[32];
#pragma unroll
    for (int k2 = 0; k2 < 32; k2++)
        w[k2] = *(const unsigned long long*)(Wih + (size_t)r * HID + 2 * k2);
    const float bias = bih[r] + bhh[r];

    const size_t row0 = (size_t)blockIdx.x * PROWS;

    float2 ld = make_float2(0.f, 0.f);
    if (tid < 256) {
        ld = *(const float2*)(src + (row0 + (tid >> 5)) * HID + 2 * (tid & 31));
        *(float2*)(&xr[0][tid >> 5][2 * (tid & 31)]) = ld;
    }
    __syncthreads();

    for (int it = 0; it < PITER; it++) {
        const int p = it & 1;
        const size_t rb = row0 + (size_t)it * 8;

        if (it + 1 < PITER && tid < 256)
            ld = *(const float2*)(src + (rb + 8 + (tid >> 5)) * HID + 2 * (tid & 31));

        unsigned long long a[4][2];
#pragma unroll
        for (int rr = 0; rr < 4; rr++) { a[rr][0] = 0ULL; a[rr][1] = 0ULL; }
#pragma unroll
        for (int m = 0; m < 16; m++) {
            unsigned long long w0 = w[2 * m], w1 = w[2 * m + 1];
#pragma unroll
            for (int rr = 0; rr < 4; rr++) {
                ulonglong2 hv = *(const ulonglong2*)(&xr[p][rl0 + rr][4 * m]);
                a[rr][0] = fma2(w0, hv.x, a[rr][0]);
                a[rr][1] = fma2(w1, hv.y, a[rr][1]);
            }
        }
#pragma unroll
        for (int rr = 0; rr < 4; rr++) {
            float v = lohi(a[rr][0]) + lohi(a[rr][1]) + bias;
            g_xp[(rb + rl0 + rr) * 256 + r] = v;
        }

        if (it + 1 < PITER && tid < 256)
            *(float2*)(&xr[p ^ 1][tid >> 5][2 * (tid & 31)]) = ld;
        __syncthreads();
    }
}

extern "C" void kernel_launch(void* const* d_in, const int* in_sizes, int n_in,
                              void* d_out, int out_size)
{
    (void)in_sizes; (void)n_in; (void)out_size;
    const float* x    = (const float*)d_in[0];
    const float* Wih0 = (const float*)d_in[1];
    const float* Whh0 = (const float*)d_in[2];
    const float* bih0 = (const float*)d_in[3];
    const float* bhh0 = (const float*)d_in[4];
    const float* Wih1 = (const float*)d_in[5];
    const float* Whh1 = (const float*)d_in[6];
    const float* bih1 = (const float*)d_in[7];
    const float* bhh1 = (const float*)d_in[8];
    const float* Wih2 = (const float*)d_in[9];
    const float* Whh2 = (const float*)d_in[10];
    const float* bih2 = (const float*)d_in[11];
    const float* bhh2 = (const float*)d_in[12];
    const float* fc_w = (const float*)d_in[13];
    const float* fc_b = (const float*)d_in[14];
    float* out = (float*)d_out;

    dim3 rgrid(BB / 4), rblock(512);
    dim3 pgrid(PCTAS), pblock(512);

    lstm_rec<0><<<rgrid, rblock>>>(x, Wih0, Whh0, bih0, bhh0, nullptr, nullptr, nullptr);
    lstm_proj<0><<<pgrid, pblock>>>(Wih1, bih1, bhh1);
    lstm_rec<1><<<rgrid, rblock>>>(nullptr, nullptr, Whh1, nullptr, nullptr, nullptr, nullptr, nullptr);
    lstm_proj<1><<<pgrid, pblock>>>(Wih2, bih2, bhh2);
    lstm_rec<2><<<rgrid, rblock>>>(nullptr, nullptr, Whh2, nullptr, nullptr, fc_w, fc_b, out);
}

// round 9
// speedup vs baseline: 2.6134x; 1.1000x over previous
#include <cuda_runtime.h>
#include <cstdint>
#include <cstddef>

// 3-layer LSTM (H=64), S=2048, B=512, FC(64->2).
// rec: thread owns all 4 gate rows of one column (K-quarter each, 64 weight
//      regs), butterfly merge over kq, LOCAL c/h update, ONE named barrier
//      per step, double-buffered h, fma2:LDS = 8.
// proj: thread owns rows (r7, r7+128) x K-half (64 weight regs), one shfl
//       merge, coalesced 64B writes.
// R8 fix: MODE-0 xsm staging is now per-group (t8 < 8 writers in EACH group),
//         so x writers share the group's named barrier with its readers.

#define SQ   2048
#define BB   512
#define HID  64

static __device__ float g_bufA[(size_t)SQ * BB * HID];
static __device__ float g_bufB[(size_t)SQ * BB * HID];
static __device__ float g_xp  [(size_t)SQ * BB * 256];

__device__ __forceinline__ unsigned long long fma2(unsigned long long a,
                                                   unsigned long long b,
                                                   unsigned long long c) {
    unsigned long long d;
    asm("fma.rn.f32x2 %0, %1, %2, %3;" : "=l"(d) : "l"(a), "l"(b), "l"(c));
    return d;
}
__device__ __forceinline__ float lohi(unsigned long long u) {
    union { unsigned long long v; float2 f; } c; c.v = u;
    return c.f.x + c.f.y;
}
__device__ __forceinline__ float ex2a(float x) {
    float y; asm("ex2.approx.f32 %0, %1;" : "=f"(y) : "f"(x)); return y;
}
__device__ __forceinline__ float rcpa(float x) {
    float y; asm("rcp.approx.f32 %0, %1;" : "=f"(y) : "f"(x)); return y;
}
__device__ __forceinline__ float sigf(float x) {
    return rcpa(1.0f + ex2a(-1.4426950408889634f * x));
}
__device__ __forceinline__ float tanh_(float x) {
    return 2.0f * rcpa(1.0f + ex2a(-2.8853900817779268f * x)) - 1.0f;
}

// ---------------------------------------------------------------------------
// Recurrence. grid=128 CTAs x 512 threads; grp = tid>>8 owns 2 batches.
// t8 = tid&255: kq = t8&3 (K-quarter, lane bits 0-1), r6 = t8>>2 (column).
// Thread holds Whh rows {r6, 64+r6, 128+r6, 192+r6}, K-quarter kq
// (4 x 16 floats = 64 regs). Partial sums merged by shfl butterfly; lane
// finalizes batch fb = kq>>1, does the c/h update locally (c replicated in
// the kq-pair). hq double-buffered, ONE bar.sync(grp+1,256) per step.
// MODE: 0 = layer0 (x inline, h->bufA), 1 = mid (xp in, h->bufB),
//       2 = final (xp in, FC->out).
// ---------------------------------------------------------------------------
template <int MODE>
__global__ void __launch_bounds__(512, 1)
lstm_rec(const float* __restrict__ xin,
         const float* __restrict__ Wih, const float* __restrict__ Whh,
         const float* __restrict__ bih, const float* __restrict__ bhh,
         const float* __restrict__ fcw, const float* __restrict__ fcb,
         float* __restrict__ out)
{
    // h[col j] at hq[buf][local batch][j>>4][j&15]; quarter stride 20 floats
    // (80B): 16B-aligned AND the 4 kq broadcast groups hit disjoint banks.
    __shared__ __align__(16) float hq[2][4][4][20];
    __shared__ __align__(16) float4 xsm[2][4];        // MODE 0 only

    const int tid = threadIdx.x;
    const int grp = tid >> 8;
    const int t8  = tid & 255;
    const int kq  = t8 & 3;
    const int r6  = t8 >> 2;
    const int fb  = kq >> 1;                 // batch this lane finalizes
    const int lb  = 2 * grp + fb;            // local batch 0..3
    const int gb  = blockIdx.x * 4 + lb;     // global batch
    const int lb0 = 2 * grp, lb1 = 2 * grp + 1;
    // MODE 0 x-staging: per-group writers (t8 < 8), batch 2grp + (t8>>2)
    const int xlb = 2 * grp + ((t8 >> 2) & 1);
    const int xgb = blockIdx.x * 4 + xlb;

    // Whh rows 64g+r6, K-quarter kq: 4 x 8 ull = 64 regs
    unsigned long long w[4][8];
#pragma unroll
    for (int g = 0; g < 4; g++)
#pragma unroll
        for (int m2 = 0; m2 < 8; m2++)
            w[g][m2] = *(const unsigned long long*)
                (Whh + (size_t)(64 * g + r6) * HID + 16 * kq + 2 * m2);

    float4 wi[4]; float bias[4];
    if (MODE == 0) {
#pragma unroll
        for (int g = 0; g < 4; g++) {
            wi[g]   = *(const float4*)(Wih + (size_t)(64 * g + r6) * 4);
            bias[g] = bih[64 * g + r6] + bhh[64 * g + r6];
        }
    }

    float c = 0.f;
    if ((kq & 1) == 0) hq[0][lb][r6 >> 4][r6 & 15] = 0.f;

    // xp queues (prefetch distance 2) for batch fb, rows 64g+r6
    const size_t xstr = (size_t)BB * 256;
    const float* xb = g_xp + (size_t)gb * 256 + r6;
    float xq[4], xm[4];
    if (MODE != 0) {
#pragma unroll
        for (int g = 0; g < 4; g++) {
            xq[g] = xb[64 * g];
            xm[g] = xb[xstr + 64 * g];
        }
    } else if (t8 < 8) {
        xsm[0][xlb] = *(const float4*)(xin + (size_t)xgb * SQ * 4);
    }
    __syncthreads();

    float* dst = (MODE == 0) ? g_bufA : g_bufB;

    for (int t = 0; t < SQ; t++) {
        const int p = t & 1;

        // prefetch t+2 xp / t+1 x
        float xn[4]; float4 xnv;
        if (MODE != 0) {
            if (t + 2 < SQ) {
                const float* q = xb + (size_t)(t + 2) * xstr;
#pragma unroll
                for (int g = 0; g < 4; g++) xn[g] = q[64 * g];
            } else {
#pragma unroll
                for (int g = 0; g < 4; g++) xn[g] = 0.f;
            }
        } else if (t8 < 8 && t + 1 < SQ) {
            xnv = *(const float4*)(xin + ((size_t)xgb * SQ + t + 1) * 4);
        }

        // ---- GEMM: 4 gate rows x 2 batches, K-quarter kq ----
        unsigned long long acc[4][2];
#pragma unroll
        for (int g = 0; g < 4; g++) { acc[g][0] = 0ULL; acc[g][1] = 0ULL; }
#pragma unroll
        for (int m = 0; m < 4; m++) {
            ulonglong2 h0 = *(const ulonglong2*)(&hq[p][lb0][kq][4 * m]);
            ulonglong2 h1 = *(const ulonglong2*)(&hq[p][lb1][kq][4 * m]);
#pragma unroll
            for (int g = 0; g < 4; g++) {
                acc[g][0] = fma2(w[g][2 * m],     h0.x, acc[g][0]);
                acc[g][0] = fma2(w[g][2 * m + 1], h0.y, acc[g][0]);
                acc[g][1] = fma2(w[g][2 * m],     h1.x, acc[g][1]);
                acc[g][1] = fma2(w[g][2 * m + 1], h1.y, acc[g][1]);
            }
        }
        float S[4][2];
#pragma unroll
        for (int g = 0; g < 4; g++) {
            S[g][0] = lohi(acc[g][0]);
            S[g][1] = lohi(acc[g][1]);
        }
        if (MODE == 0 && kq == 0) {
            float4 xa  = xsm[p][lb0];
            float4 xbv = xsm[p][lb1];
#pragma unroll
            for (int g = 0; g < 4; g++) {
                S[g][0] += wi[g].x * xa.x + wi[g].y * xa.y + wi[g].z * xa.z + wi[g].w * xa.w;
                S[g][1] += wi[g].x * xbv.x + wi[g].y * xbv.y + wi[g].z * xbv.z + wi[g].w * xbv.w;
            }
        }

        // ---- merge over kq: round 1 (xor 1) then targeted round 2 (xor 2)
        float full[4];
#pragma unroll
        for (int g = 0; g < 4; g++) {
            S[g][0] += __shfl_xor_sync(0xffffffffu, S[g][0], 1);
            S[g][1] += __shfl_xor_sync(0xffffffffu, S[g][1], 1);
        }
#pragma unroll
        for (int g = 0; g < 4; g++) {
            float own  = fb ? S[g][1] : S[g][0];
            float send = fb ? S[g][0] : S[g][1];
            float recv = __shfl_xor_sync(0xffffffffu, send, 2);
            full[g] = own + recv;
        }

#pragma unroll
        for (int g = 0; g < 4; g++)
            full[g] += (MODE == 0) ? bias[g] : xq[g];

        // ---- local LSTM update (c replicated across the kq pair) ----
        float iv = sigf(full[0]);
        float fv = sigf(full[1]);
        float gv = tanh_(full[2]);
        float ov = sigf(full[3]);
        c = fv * c + iv * gv;
        float h = ov * tanh_(c);

        if ((kq & 1) == 0) {
            hq[p ^ 1][lb][r6 >> 4][r6 & 15] = h;
            if (MODE != 2)
                dst[((size_t)t * BB + gb) * HID + r6] = h;
        }
        if (MODE == 0) {
            if (t8 < 8 && t + 1 < SQ) xsm[(t + 1) & 1][xlb] = xnv;
        } else {
#pragma unroll
            for (int g = 0; g < 4; g++) { xq[g] = xm[g]; xm[g] = xn[g]; }
        }
        asm volatile("bar.sync %0, 256;" :: "r"(grp + 1) : "memory");
    }

    if (MODE == 2) {
        __syncthreads();   // cross-group visibility of hq[0]
        if (tid < 8) {
            int b = tid >> 1, o = tid & 1;
            float s = fcb[o];
#pragma unroll
            for (int j = 0; j < HID; j++)
                s += hq[0][b][j >> 4][j & 15] * fcw[o * HID + j];
            out[(blockIdx.x * 4 + b) * 2 + o] = s;
        }
    }
}

// ---------------------------------------------------------------------------
// Projection: g_xp[row][col] = Wih[col,:] . src[row,:] + bih[col] + bhh[col]
// grid=1024 x 512. kh = tid&1 (K-half, lane bit 0), r7 = (tid>>1)&127,
// dh = tid>>8 (data-row half). Thread: rows (r7, r7+128) x K-half kh
// (64 weight regs), 4 data rows/iter. One xor-1 shfl merge; lane kh writes
// col r7+128*kh (16 consecutive cols per half-warp -> 64B segments).
// ---------------------------------------------------------------------------
#define PCTAS 1024
#define PROWS ((SQ * BB) / PCTAS)     // 1024
#define PITER (PROWS / 8)             // 128

template <int SRCB>
__global__ void __launch_bounds__(512, 1)
lstm_proj(const float* __restrict__ Wih,
          const float* __restrict__ bih, const float* __restrict__ bhh)
{
    const float* src = (SRCB == 0) ? g_bufA : g_bufB;
    __shared__ __align__(16) float xr[2][8][2][36];   // [buf][row][half][32+pad]

    const int tid = threadIdx.x;
    const int kh  = tid & 1;
    const int r7  = (tid >> 1) & 127;
    const int dh  = tid >> 8;
    const int col = r7 + 128 * kh;

    unsigned long long w0[16], w1[16];
#pragma unroll
    for (int m2 = 0; m2 < 16; m2++) {
        w0[m2] = *(const unsigned long long*)(Wih + (size_t)r7 * HID + 32 * kh + 2 * m2);
        w1[m2] = *(const unsigned long long*)(Wih + (size_t)(r7 + 128) * HID + 32 * kh + 2 * m2);
    }
    const float bias = bih[col] + bhh[col];

    const size_t row0 = (size_t)blockIdx.x * PROWS;

    float2 ld = make_float2(0.f, 0.f);
    if (tid < 256) {
        ld = *(const float2*)(src + (row0 + (tid >> 5)) * HID + 2 * (tid & 31));
        *(float2*)(&xr[0][tid >> 5][(tid & 31) >> 4][(2 * (tid & 31)) & 31]) = ld;
    }
    __syncthreads();

    for (int it = 0; it < PITER; it++) {
        const int p = it & 1;
        const size_t rb = row0 + (size_t)it * 8;

        if (it + 1 < PITER && tid < 256)
            ld = *(const float2*)(src + (rb + 8 + (tid >> 5)) * HID + 2 * (tid & 31));

        unsigned long long a0[4], a1[4];
#pragma unroll
        for (int dr = 0; dr < 4; dr++) { a0[dr] = 0ULL; a1[dr] = 0ULL; }
#pragma unroll
        for (int m = 0; m < 8; m++) {
#pragma unroll
            for (int dr = 0; dr < 4; dr++) {
                ulonglong2 hv = *(const ulonglong2*)(&xr[p][4 * dh + dr][kh][4 * m]);
                a0[dr] = fma2(w0[2 * m],     hv.x, a0[dr]);
                a0[dr] = fma2(w0[2 * m + 1], hv.y, a0[dr]);
                a1[dr] = fma2(w1[2 * m],     hv.x, a1[dr]);
                a1[dr] = fma2(w1[2 * m + 1], hv.y, a1[dr]);
            }
        }
#pragma unroll
        for (int dr = 0; dr < 4; dr++) {
            float s0 = lohi(a0[dr]);
            float s1 = lohi(a1[dr]);
            float send = kh ? s0 : s1;       // pass the row I don't finalize
            float recv = __shfl_xor_sync(0xffffffffu, send, 1);
            float full = (kh ? s1 : s0) + recv + bias;
            g_xp[(rb + 4 * dh + dr) * 256 + col] = full;
        }

        if (it + 1 < PITER && tid < 256)
            *(float2*)(&xr[p ^ 1][tid >> 5][(tid & 31) >> 4][(2 * (tid & 31)) & 31]) = ld;
        __syncthreads();
    }
}

extern "C" void kernel_launch(void* const* d_in, const int* in_sizes, int n_in,
                              void* d_out, int out_size)
{
    (void)in_sizes; (void)n_in; (void)out_size;
    const float* x    = (const float*)d_in[0];
    const float* Wih0 = (const float*)d_in[1];
    const float* Whh0 = (const float*)d_in[2];
    const float* bih0 = (const float*)d_in[3];
    const float* bhh0 = (const float*)d_in[4];
    const float* Wih1 = (const float*)d_in[5];
    const float* Whh1 = (const float*)d_in[6];
    const float* bih1 = (const float*)d_in[7];
    const float* bhh1 = (const float*)d_in[8];
    const float* Wih2 = (const float*)d_in[9];
    const float* Whh2 = (const float*)d_in[10];
    const float* bih2 = (const float*)d_in[11];
    const float* bhh2 = (const float*)d_in[12];
    const float* fc_w = (const float*)d_in[13];
    const float* fc_b = (const float*)d_in[14];
    float* out = (float*)d_out;

    dim3 rgrid(BB / 4), rblock(512);
    dim3 pgrid(PCTAS), pblock(512);

    lstm_rec<0><<<rgrid, rblock>>>(x, Wih0, Whh0, bih0, bhh0, nullptr, nullptr, nullptr);
    lstm_proj<0><<<pgrid, pblock>>>(Wih1, bih1, bhh1);
    lstm_rec<1><<<rgrid, rblock>>>(nullptr, nullptr, Whh1, nullptr, nullptr, nullptr, nullptr, nullptr);
    lstm_proj<1><<<pgrid, pblock>>>(Wih2, bih2, bhh2);
    lstm_rec<2><<<rgrid, rblock>>>(nullptr, nullptr, Whh2, nullptr, nullptr, fc_w, fc_b, out);
}

// round 10
// speedup vs baseline: 2.9014x; 1.1102x over previous
#include <cuda_runtime.h>
#include <cstdint>
#include <cstddef>

// 3-layer LSTM (H=64), S=2048, B=512, FC(64->2).
// rec: thread owns all 4 gate rows of one column (K-quarter each, 64 weight
//      regs), butterfly merge over kq, LOCAL c/h update, ONE named barrier
//      per step, double-buffered h. R10: activations via tanh.approx.f32
//      (1 MUFU each) -> SMSP MUFU pressure halved.
// proj: R10: 256-thread CTAs, 2 CTAs/SM (32 warps/SM) to hide barrier tails.

#define SQ   2048
#define BB   512
#define HID  64

static __device__ float g_bufA[(size_t)SQ * BB * HID];
static __device__ float g_bufB[(size_t)SQ * BB * HID];
static __device__ float g_xp  [(size_t)SQ * BB * 256];

__device__ __forceinline__ unsigned long long fma2(unsigned long long a,
                                                   unsigned long long b,
                                                   unsigned long long c) {
    unsigned long long d;
    asm("fma.rn.f32x2 %0, %1, %2, %3;" : "=l"(d) : "l"(a), "l"(b), "l"(c));
    return d;
}
__device__ __forceinline__ float lohi(unsigned long long u) {
    union { unsigned long long v; float2 f; } c; c.v = u;
    return c.f.x + c.f.y;
}
__device__ __forceinline__ float tanha(float x) {
    float y; asm("tanh.approx.f32 %0, %1;" : "=f"(y) : "f"(x)); return y;
}
__device__ __forceinline__ float sigf(float x) {
    return fmaf(0.5f, tanha(0.5f * x), 0.5f);
}

// ---------------------------------------------------------------------------
// Recurrence. grid=128 CTAs x 512 threads; grp = tid>>8 owns 2 batches.
// t8 = tid&255: kq = t8&3 (K-quarter), r6 = t8>>2 (column). Thread holds
// Whh rows {r6, 64+r6, 128+r6, 192+r6}, K-quarter kq (64 regs). Butterfly
// merge over kq; lane finalizes batch fb = kq>>1 locally. hq double-buffered,
// ONE bar.sync(grp+1,256) per step.
// MODE: 0 = layer0 (x inline, h->bufA), 1 = mid (xp in, h->bufB),
//       2 = final (xp in, FC->out).
// ---------------------------------------------------------------------------
template <int MODE>
__global__ void __launch_bounds__(512, 1)
lstm_rec(const float* __restrict__ xin,
         const float* __restrict__ Wih, const float* __restrict__ Whh,
         const float* __restrict__ bih, const float* __restrict__ bhh,
         const float* __restrict__ fcw, const float* __restrict__ fcb,
         float* __restrict__ out)
{
    // h[col j] at hq[buf][local batch][j>>4][j&15]; quarter stride 20 floats
    // (80B): 16B-aligned, 4 kq broadcast groups on disjoint banks.
    __shared__ __align__(16) float hq[2][4][4][20];
    __shared__ __align__(16) float4 xsm[2][4];        // MODE 0 only

    const int tid = threadIdx.x;
    const int grp = tid >> 8;
    const int t8  = tid & 255;
    const int kq  = t8 & 3;
    const int r6  = t8 >> 2;
    const int fb  = kq >> 1;                 // batch this lane finalizes
    const int lb  = 2 * grp + fb;            // local batch 0..3
    const int gb  = blockIdx.x * 4 + lb;     // global batch
    const int lb0 = 2 * grp, lb1 = 2 * grp + 1;
    // MODE 0 x-staging: per-group writers (t8 < 8), batch 2grp + (t8>>2)
    const int xlb = 2 * grp + ((t8 >> 2) & 1);
    const int xgb = blockIdx.x * 4 + xlb;

    unsigned long long w[4][8];
#pragma unroll
    for (int g = 0; g < 4; g++)
#pragma unroll
        for (int m2 = 0; m2 < 8; m2++)
            w[g][m2] = *(const unsigned long long*)
                (Whh + (size_t)(64 * g + r6) * HID + 16 * kq + 2 * m2);

    float4 wi[4]; float bias[4];
    if (MODE == 0) {
#pragma unroll
        for (int g = 0; g < 4; g++) {
            wi[g]   = *(const float4*)(Wih + (size_t)(64 * g + r6) * 4);
            bias[g] = bih[64 * g + r6] + bhh[64 * g + r6];
        }
    }

    float c = 0.f;
    if ((kq & 1) == 0) hq[0][lb][r6 >> 4][r6 & 15] = 0.f;

    const size_t xstr = (size_t)BB * 256;
    const float* xb = g_xp + (size_t)gb * 256 + r6;
    float xq[4], xm[4];
    if (MODE != 0) {
#pragma unroll
        for (int g = 0; g < 4; g++) {
            xq[g] = xb[64 * g];
            xm[g] = xb[xstr + 64 * g];
        }
    } else if (t8 < 8) {
        xsm[0][xlb] = *(const float4*)(xin + (size_t)xgb * SQ * 4);
    }
    __syncthreads();

    float* dst = (MODE == 0) ? g_bufA : g_bufB;

    for (int t = 0; t < SQ; t++) {
        const int p = t & 1;

        float xn[4]; float4 xnv;
        if (MODE != 0) {
            if (t + 2 < SQ) {
                const float* q = xb + (size_t)(t + 2) * xstr;
#pragma unroll
                for (int g = 0; g < 4; g++) xn[g] = q[64 * g];
            } else {
#pragma unroll
                for (int g = 0; g < 4; g++) xn[g] = 0.f;
            }
        } else if (t8 < 8 && t + 1 < SQ) {
            xnv = *(const float4*)(xin + ((size_t)xgb * SQ + t + 1) * 4);
        }

        // ---- GEMM: 4 gate rows x 2 batches, K-quarter kq ----
        unsigned long long acc[4][2];
#pragma unroll
        for (int g = 0; g < 4; g++) { acc[g][0] = 0ULL; acc[g][1] = 0ULL; }
#pragma unroll
        for (int m = 0; m < 4; m++) {
            ulonglong2 h0 = *(const ulonglong2*)(&hq[p][lb0][kq][4 * m]);
            ulonglong2 h1 = *(const ulonglong2*)(&hq[p][lb1][kq][4 * m]);
#pragma unroll
            for (int g = 0; g < 4; g++) {
                acc[g][0] = fma2(w[g][2 * m],     h0.x, acc[g][0]);
                acc[g][0] = fma2(w[g][2 * m + 1], h0.y, acc[g][0]);
                acc[g][1] = fma2(w[g][2 * m],     h1.x, acc[g][1]);
                acc[g][1] = fma2(w[g][2 * m + 1], h1.y, acc[g][1]);
            }
        }
        float S[4][2];
#pragma unroll
        for (int g = 0; g < 4; g++) {
            S[g][0] = lohi(acc[g][0]);
            S[g][1] = lohi(acc[g][1]);
        }
        if (MODE == 0 && kq == 0) {
            float4 xa  = xsm[p][lb0];
            float4 xbv = xsm[p][lb1];
#pragma unroll
            for (int g = 0; g < 4; g++) {
                S[g][0] += wi[g].x * xa.x + wi[g].y * xa.y + wi[g].z * xa.z + wi[g].w * xa.w;
                S[g][1] += wi[g].x * xbv.x + wi[g].y * xbv.y + wi[g].z * xbv.z + wi[g].w * xbv.w;
            }
        }

        // ---- merge over kq ----
        float full[4];
#pragma unroll
        for (int g = 0; g < 4; g++) {
            S[g][0] += __shfl_xor_sync(0xffffffffu, S[g][0], 1);
            S[g][1] += __shfl_xor_sync(0xffffffffu, S[g][1], 1);
        }
#pragma unroll
        for (int g = 0; g < 4; g++) {
            float own  = fb ? S[g][1] : S[g][0];
            float send = fb ? S[g][0] : S[g][1];
            float recv = __shfl_xor_sync(0xffffffffu, send, 2);
            full[g] = own + recv;
        }
#pragma unroll
        for (int g = 0; g < 4; g++)
            full[g] += (MODE == 0) ? bias[g] : xq[g];

        // ---- local LSTM update (tanh.approx activations) ----
        float iv = sigf(full[0]);
        float fv = sigf(full[1]);
        float gv = tanha(full[2]);
        float ov = sigf(full[3]);
        c = fv * c + iv * gv;
        float h = ov * tanha(c);

        if ((kq & 1) == 0) {
            hq[p ^ 1][lb][r6 >> 4][r6 & 15] = h;
            if (MODE != 2)
                dst[((size_t)t * BB + gb) * HID + r6] = h;
        }
        if (MODE == 0) {
            if (t8 < 8 && t + 1 < SQ) xsm[(t + 1) & 1][xlb] = xnv;
        } else {
#pragma unroll
            for (int g = 0; g < 4; g++) { xq[g] = xm[g]; xm[g] = xn[g]; }
        }
        asm volatile("bar.sync %0, 256;" :: "r"(grp + 1) : "memory");
    }

    if (MODE == 2) {
        __syncthreads();
        if (tid < 8) {
            int b = tid >> 1, o = tid & 1;
            float s = fcb[o];
#pragma unroll
            for (int j = 0; j < HID; j++)
                s += hq[0][b][j >> 4][j & 15] * fcw[o * HID + j];
            out[(blockIdx.x * 4 + b) * 2 + o] = s;
        }
    }
}

// ---------------------------------------------------------------------------
// Projection: g_xp[row][col] = Wih[col,:] . src[row,:] + bih[col] + bhh[col]
// R10: grid=2048 x 256 threads, 2 CTAs/SM. kh = tid&1, r7 = (tid>>1)&127.
// Thread: rows (r7, r7+128) x K-half kh (64 weight regs), 4 data rows/iter.
// One xor-1 shfl merge; coalesced 64B-segment writes. Double-buffered smem.
// ---------------------------------------------------------------------------
#define PCTAS 2048
#define PROWS ((SQ * BB) / PCTAS)     // 512
#define PITER (PROWS / 4)             // 128

template <int SRCB>
__global__ void __launch_bounds__(256, 2)
lstm_proj(const float* __restrict__ Wih,
          const float* __restrict__ bih, const float* __restrict__ bhh)
{
    const float* src = (SRCB == 0) ? g_bufA : g_bufB;
    __shared__ __align__(16) float xr[2][4][2][36];   // [buf][row][half][32+pad]

    const int tid = threadIdx.x;
    const int kh  = tid & 1;
    const int r7  = tid >> 1;
    const int col = r7 + 128 * kh;

    unsigned long long w0[16], w1[16];
#pragma unroll
    for (int m2 = 0; m2 < 16; m2++) {
        w0[m2] = *(const unsigned long long*)(Wih + (size_t)r7 * HID + 32 * kh + 2 * m2);
        w1[m2] = *(const unsigned long long*)(Wih + (size_t)(r7 + 128) * HID + 32 * kh + 2 * m2);
    }
    const float bias = bih[col] + bhh[col];

    const size_t row0 = (size_t)blockIdx.x * PROWS;

    float2 ld = make_float2(0.f, 0.f);
    if (tid < 128) {
        ld = *(const float2*)(src + (row0 + (tid >> 5)) * HID + 2 * (tid & 31));
        *(float2*)(&xr[0][tid >> 5][(tid & 31) >> 4][(2 * (tid & 31)) & 31]) = ld;
    }
    __syncthreads();

    for (int it = 0; it < PITER; it++) {
        const int p = it & 1;
        const size_t rb = row0 + (size_t)it * 4;

        if (it + 1 < PITER && tid < 128)
            ld = *(const float2*)(src + (rb + 4 + (tid >> 5)) * HID + 2 * (tid & 31));

        unsigned long long a0[4], a1[4];
#pragma unroll
        for (int dr = 0; dr < 4; dr++) { a0[dr] = 0ULL; a1[dr] = 0ULL; }
#pragma unroll
        for (int m = 0; m < 8; m++) {
#pragma unroll
            for (int dr = 0; dr < 4; dr++) {
                ulonglong2 hv = *(const ulonglong2*)(&xr[p][dr][kh][4 * m]);
                a0[dr] = fma2(w0[2 * m],     hv.x, a0[dr]);
                a0[dr] = fma2(w0[2 * m + 1], hv.y, a0[dr]);
                a1[dr] = fma2(w1[2 * m],     hv.x, a1[dr]);
                a1[dr] = fma2(w1[2 * m + 1], hv.y, a1[dr]);
            }
        }
#pragma unroll
        for (int dr = 0; dr < 4; dr++) {
            float s0 = lohi(a0[dr]);
            float s1 = lohi(a1[dr]);
            float send = kh ? s0 : s1;       // pass the row I don't finalize
            float recv = __shfl_xor_sync(0xffffffffu, send, 1);
            float full = (kh ? s1 : s0) + recv + bias;
            g_xp[(rb + dr) * 256 + col] = full;
        }

        if (it + 1 < PITER && tid < 128)
            *(float2*)(&xr[p ^ 1][tid >> 5][(tid & 31) >> 4][(2 * (tid & 31)) & 31]) = ld;
        __syncthreads();
    }
}

extern "C" void kernel_launch(void* const* d_in, const int* in_sizes, int n_in,
                              void* d_out, int out_size)
{
    (void)in_sizes; (void)n_in; (void)out_size;
    const float* x    = (const float*)d_in[0];
    const float* Wih0 = (const float*)d_in[1];
    const float* Whh0 = (const float*)d_in[2];
    const float* bih0 = (const float*)d_in[3];
    const float* bhh0 = (const float*)d_in[4];
    const float* Wih1 = (const float*)d_in[5];
    const float* Whh1 = (const float*)d_in[6];
    const float* bih1 = (const float*)d_in[7];
    const float* bhh1 = (const float*)d_in[8];
    const float* Wih2 = (const float*)d_in[9];
    const float* Whh2 = (const float*)d_in[10];
    const float* bih2 = (const float*)d_in[11];
    const float* bhh2 = (const float*)d_in[12];
    const float* fc_w = (const float*)d_in[13];
    const float* fc_b = (const float*)d_in[14];
    float* out = (float*)d_out;

    dim3 rgrid(BB / 4), rblock(512);
    dim3 pgrid(PCTAS), pblock(256);

    lstm_rec<0><<<rgrid, rblock>>>(x, Wih0, Whh0, bih0, bhh0, nullptr, nullptr, nullptr);
    lstm_proj<0><<<pgrid, pblock>>>(Wih1, bih1, bhh1);
    lstm_rec<1><<<rgrid, rblock>>>(nullptr, nullptr, Whh1, nullptr, nullptr, nullptr, nullptr, nullptr);
    lstm_proj<1><<<pgrid, pblock>>>(Wih2, bih2, bhh2);
    lstm_rec<2><<<rgrid, rblock>>>(nullptr, nullptr, Whh2, nullptr, nullptr, fc_w, fc_b, out);
}